// round 12
// baseline (speedup 1.0000x reference)
#include <cuda_runtime.h>
#include <math.h>

#define NSENT 8192
#define C     1024
#define NCTA  64                  // producer CTAs per direction
#define NTHREADS 544              // 16 compute warps + 1 poller warp
#define NCTA_TOTAL (2*NCTA)
#define FSTRIDE 8
#define ROWS_PER_CTA (NSENT / NCTA_TOTAL)   // 64

// -------- device scratch (no allocations allowed) --------
__device__ __align__(16) float g_E [C*C];   // exp(T) row-major [k][j]  (beta)
__device__ __align__(16) float g_ET[C*C];   // transpose [j][k]         (alpha)
__device__ __align__(16) float g_beta[(size_t)NSENT*C];
__device__ __align__(16) float g_q[2][2][C];        // [dir][buf][class]
__device__ unsigned g_flag[2][NCTA*FSTRIDE];        // per-producer step flags
__device__ double   g_offA[NSENT];
__device__ double   g_offB[NSENT];
__device__ double   g_Zbase;
__device__ unsigned g_jflags[NCTA_TOTAL*FSTRIDE];

// ---- global-scope primitives ----
__device__ __forceinline__ unsigned ld_acq(const unsigned* p) {
    unsigned v;
    asm volatile("ld.acquire.gpu.global.u32 %0, [%1];" : "=r"(v) : "l"(p) : "memory");
    return v;
}
__device__ __forceinline__ void st_rel(unsigned* p, unsigned v) {
    asm volatile("st.release.gpu.global.u32 [%0], %1;" :: "l"(p), "r"(v) : "memory");
}
__device__ __forceinline__ void st_f32_cg(float* p, float v) {
    asm volatile("st.global.cg.f32 [%0], %1;" :: "l"(p), "f"(v) : "memory");
}
// ---- cta-scope shared primitives ----
__device__ __forceinline__ unsigned smaddr(const void* p) {
    return (unsigned)__cvta_generic_to_shared(p);
}
__device__ __forceinline__ unsigned ld_acq_sh(unsigned a) {
    unsigned v;
    asm volatile("ld.acquire.cta.shared.u32 %0, [%1];" : "=r"(v) : "r"(a) : "memory");
    return v;
}
__device__ __forceinline__ void st_rel_sh(unsigned a, unsigned v) {
    asm volatile("st.release.cta.shared.u32 [%0], %1;" :: "r"(a), "r"(v) : "memory");
}
__device__ __forceinline__ void red_rel_sh(unsigned a, unsigned v) {
    asm volatile("red.release.cta.shared.add.u32 [%0], %1;" :: "r"(a), "r"(v) : "memory");
}
__device__ __forceinline__ unsigned atom_addret_sh(unsigned a, unsigned v) {
    unsigned o;
    asm volatile("atom.acq_rel.cta.shared.add.u32 %0, [%1], %2;"
                 : "=r"(o) : "r"(a), "r"(v) : "memory");
    return o;
}
__device__ __forceinline__ float frcp(float x) {
    float r;
    asm("rcp.approx.f32 %0, %1;" : "=f"(r) : "f"(x));
    return r;
}

// -------- init kernel --------
__global__ void crf_init(const float* __restrict__ T) {
    int idx = blockIdx.x * blockDim.x + threadIdx.x;
    if (idx < C*C) {
        float e = expf(T[idx]);
        g_E[idx] = e;
        int k = idx / C, j = idx % C;
        g_ET[j*C + k] = e;
    }
    if (idx < 2*NCTA*FSTRIDE)     ((unsigned*)g_flag)[idx] = 0u;
    if (idx < NCTA_TOTAL*FSTRIDE) g_jflags[idx] = 0u;
}

// -------- persistent forward+backward kernel --------
__global__ void __launch_bounds__(NTHREADS, 1) crf_main(const float* __restrict__ scores,
                                                        float* __restrict__ out) {
    const int  cta    = blockIdx.x;
    const bool isBeta = (cta >= NCTA);
    const int  dir    = isBeta ? 1 : 0;
    const int  grp    = isBeta ? (cta - NCTA) : cta;
    const int  warp   = threadIdx.x >> 5;
    const int  lane   = threadIdx.x & 31;

    __shared__ __align__(16) float q_sm[2][C];  // double-buffered staged vector
    __shared__ unsigned gc[4];                  // per-group cumulative stage counts
    __shared__ unsigned done[16];               // per-compute-warp finished step
    __shared__ unsigned lcnt;                   // local publish counter (cumulative)
    __shared__ float    redsum[17];
    __shared__ float    k_sm[ROWS_PER_CTA];

    if (threadIdx.x < 4)  gc[threadIdx.x] = 0u;
    if (threadIdx.x < 16) done[threadIdx.x] = 0u;
    if (threadIdx.x == 0) lcnt = 0u;
    __syncthreads();

    float*    rowsOut = isBeta ? g_beta : out;
    double*   offArr  = isBeta ? g_offB : g_offA;
    unsigned* flagArr = g_flag[dir];
    const unsigned lcntA = smaddr(&lcnt);
    const unsigned gcA   = smaddr(&gc[0]);
    const unsigned doneA = smaddr(&done[0]);

    if (warp < 16) {
        // ============ COMPUTE WARP: owns column j ============
        const int j = grp * 16 + warp;
        float4 Ereg[8];
        {
            const float* Emat = isBeta ? g_E : g_ET;
            const float4* Erow = (const float4*)(Emat + (size_t)j * C);
            #pragma unroll
            for (int u = 0; u < 8; u++) Ereg[u] = Erow[u*32 + lane];
        }
        const bool keeper = (grp == 0 && warp == 0);
        double Cd = 0.0;
        float s_pref = 0.f, es_pref = 0.f;

        // ---- step 0 ----
        {
            const int row0 = isBeta ? (NSENT - 1) : 0;
            if (lane == 0) {
                float a0 = __ldg(&scores[(size_t)row0 * C + j]);
                rowsOut[(size_t)row0 * C + j] = a0;
                st_f32_cg(&g_q[dir][0][j], expf(a0));
                unsigned old = atom_addret_sh(lcntA, 1u);     // acq_rel: chains visibility
                if (old == 15u) st_rel(&flagArr[grp*FSTRIDE], 1u);
                const int row1 = isBeta ? (NSENT - 2) : 1;
                s_pref = __ldg(&scores[(size_t)row1 * C + j]);
                es_pref = expf(s_pref);
                if (keeper) offArr[row0] = 0.0;
            }
        }

        // ---- main loop: 8191 dependent rounds ----
        for (int t = 1; t < NSENT; t++) {
            const int row = isBeta ? (NSENT - 1 - t) : t;
            const int buf = (t - 1) & 1;
            float sv = s_pref, esv = es_pref;
            if (lane == 0) {
                int tn = (t + 1 < NSENT) ? (t + 1) : t;
                int rown = isBeta ? (NSENT - 1 - tn) : tn;
                s_pref = __ldg(&scores[(size_t)rown * C + j]);
            }

            float a0=0.f,a1=0.f,a2=0.f,a3=0.f;
            float m0=0.f,m1=0.f,m2=0.f,m3=0.f;
            const float4* p4 = (const float4*)q_sm[buf];
            const unsigned need = 16u * (unsigned)t;   // groups staged thru t-1
            #pragma unroll
            for (int c = 0; c < 4; c++) {
                while (ld_acq_sh(gcA + c*4) < need) { }   // group gate (LDS speed)
                #pragma unroll
                for (int uu = 0; uu < 2; uu++) {
                    const int u = c*2 + uu;
                    float4 p = p4[u*32 + lane];
                    a0 = fmaf(p.x, Ereg[u].x, a0);  m0 = fmaxf(m0, p.x);
                    a1 = fmaf(p.y, Ereg[u].y, a1);  m1 = fmaxf(m1, p.y);
                    a2 = fmaf(p.z, Ereg[u].z, a2);  m2 = fmaxf(m2, p.z);
                    a3 = fmaf(p.w, Ereg[u].w, a3);  m3 = fmaxf(m3, p.w);
                }
            }
            if (lane == 0) st_rel_sh(doneA + warp*4, (unsigned)t);  // reads done

            float acc = (a0 + a1) + (a2 + a3);
            float mxp = fmaxf(fmaxf(m0, m1), fmaxf(m2, m3));
            #pragma unroll
            for (int s = 16; s > 0; s >>= 1) {
                acc += __shfl_xor_sync(0xFFFFFFFFu, acc, s);
                mxp  = fmaxf(mxp, __shfl_xor_sync(0xFFFFFFFFu, mxp, s));
            }

            float r = frcp(mxp);                  // bitwise identical everywhere
            float q = esv * acc * r;
            if (lane == 0) {
                // publish: ONE weak store + local atom; last warp releases flag
                st_f32_cg(&g_q[dir][t & 1][j], q);
                unsigned old = atom_addret_sh(lcntA, 1u);
                if (old + 1u == 16u * (unsigned)(t + 1))
                    st_rel(&flagArr[grp*FSTRIDE], (unsigned)(t + 1));
                // off critical path:
                rowsOut[(size_t)row * C + j] = sv + logf(acc);
                if (keeper) {
                    offArr[row] = Cd;
                    Cd -= (double)logf(r);
                }
                es_pref = expf(s_pref);
            }
        }
        if (lane == 0 && keeper && !isBeta) g_Zbase = Cd;
    } else {
        // ============ POLLER WARP: lane stages producers lane, lane+32 ============
        for (int m = 0; m < NSENT - 1; m++) {
            const int buf = m & 1;
            // local buffer-free: all compute warps consumed staged step m-2
            const unsigned needd = (m >= 2) ? (unsigned)(m - 1) : 0u;
            while (!__all_sync(0xFFFFFFFFu,
                               ld_acq_sh(doneA + (lane & 15)*4) >= needd)) { }
            unsigned pending = 3u;
            while (__any_sync(0xFFFFFFFFu, pending != 0u)) {
                #pragma unroll
                for (int i = 0; i < 2; i++) {
                    if (pending & (1u << i)) {
                        const int p = lane + 32*i;
                        if (ld_acq(&flagArr[p*FSTRIDE]) >= (unsigned)(m + 1)) {
                            const float4* src = (const float4*)&g_q[dir][buf][p*16];
                            float4 v0 = __ldcg(&src[0]);
                            float4 v1 = __ldcg(&src[1]);
                            float4 v2 = __ldcg(&src[2]);
                            float4 v3 = __ldcg(&src[3]);
                            float4* dst = (float4*)&q_sm[buf][p*16];
                            dst[0] = v0; dst[1] = v1; dst[2] = v2; dst[3] = v3;
                            red_rel_sh(gcA + (p >> 4)*4, 1u);   // orders STS before gate
                            pending &= ~(1u << i);
                        }
                    }
                }
                if (__any_sync(0xFFFFFFFFu, pending != 0u)) __nanosleep(64);
            }
        }
    }

    // ---- drain + join both directions ----
    __threadfence();
    __syncthreads();
    if (threadIdx.x == 0) st_rel(&g_jflags[cta*FSTRIDE], 1u);
    if (threadIdx.x < NCTA_TOTAL) {
        const unsigned* fp = &g_jflags[threadIdx.x * FSTRIDE];
        while (ld_acq(fp) < 1u) { }
    }
    __syncthreads();

    // ---- Z = Zbase + log(sum q_final) (final alpha q in g_q[0][1]) ----
    double Zd;
    {
        float zs = 0.0f;
        if (threadIdx.x < 256) {
            float4 v = __ldcg(&((const float4*)g_q[0][1])[threadIdx.x]);
            zs = (v.x + v.y) + (v.z + v.w);
        }
        #pragma unroll
        for (int s = 16; s > 0; s >>= 1)
            zs += __shfl_xor_sync(0xFFFFFFFFu, zs, s);
        if (lane == 0) redsum[warp] = zs;
        __syncthreads();
        if (warp == 0) {
            float s = (lane < 8) ? redsum[lane] : 0.0f;
            #pragma unroll
            for (int sh = 4; sh > 0; sh >>= 1)
                s += __shfl_xor_sync(0xFFFFFFFFu, s, sh);
            if (lane == 0) redsum[0] = s;
        }
        __syncthreads();
        Zd = g_Zbase + (double)logf(redsum[0]);
    }

    // ---- per-row combine constants K[i] = offA[i] + offB[i] - Z ----
    const int rbase = cta * ROWS_PER_CTA;
    if (threadIdx.x < ROWS_PER_CTA) {
        int row = rbase + threadIdx.x;
        k_sm[threadIdx.x] = (float)(g_offA[row] + g_offB[row] - Zd);
    }
    __syncthreads();

    // ---- marginals: out = a_hat(out) + b_hat - scores + K[row] ----
    {
        const float4* b4 = (const float4*)g_beta;
        const float4* s4 = (const float4*)scores;
        float4* o4 = (float4*)out;
        const size_t base4 = (size_t)rbase * (C/4);
        const int    n4    = ROWS_PER_CTA * (C/4);
        for (int idx = threadIdx.x; idx < n4; idx += NTHREADS) {
            int   rl = idx >> 8;
            float K  = k_sm[rl];
            size_t i = base4 + idx;
            float4 av = __ldcg(&o4[i]);
            float4 b  = __ldcg(&b4[i]);
            float4 s  = __ldg(&s4[i]);
            float4 r;
            r.x = av.x + b.x - s.x + K;
            r.y = av.y + b.y - s.y + K;
            r.z = av.z + b.z - s.z + K;
            r.w = av.w + b.w - s.w + K;
            o4[i] = r;
        }
    }
}

extern "C" void kernel_launch(void* const* d_in, const int* in_sizes, int n_in,
                              void* d_out, int out_size) {
    const float* scores = (const float*)d_in[0];   // [8192*1024] f32
    const float* T      = (const float*)d_in[1];   // [1024*1024] f32
    float* out = (float*)d_out;                    // [8192*1024] f32

    crf_init<<<(C*C + 255) / 256, 256>>>(T);
    crf_main<<<NCTA_TOTAL, NTHREADS>>>(scores, out);
}

// round 13
// speedup vs baseline: 1.5500x; 1.5500x over previous
#include <cuda_runtime.h>
#include <math.h>

#define NSENT 8192
#define C     1024
#define NCTA  64                  // producer CTAs per direction
#define NWARP 8                   // 8 compute warps, 2 columns each
#define NTHREADS 256
#define NCTA_TOTAL (2*NCTA)
#define FSTRIDE 8
#define ROWS_PER_CTA (NSENT / NCTA_TOTAL)   // 64

// -------- device scratch (no allocations allowed) --------
__device__ __align__(16) float g_E [C*C];   // exp(T) row-major [k][j]  (beta)
__device__ __align__(16) float g_ET[C*C];   // transpose [j][k]         (alpha)
__device__ __align__(16) float g_beta[(size_t)NSENT*C];
__device__ __align__(16) float g_q[2][2][C];       // [dir][buf][class]
__device__ unsigned g_cnt[2][NCTA*FSTRIDE];        // cumulative publish counters
__device__ double   g_offA[NSENT];
__device__ double   g_offB[NSENT];
__device__ double   g_Zbase;
__device__ unsigned g_jflags[NCTA_TOTAL*FSTRIDE];

__device__ __forceinline__ unsigned ld_acq(const unsigned* p) {
    unsigned v;
    asm volatile("ld.acquire.gpu.global.u32 %0, [%1];" : "=r"(v) : "l"(p) : "memory");
    return v;
}
__device__ __forceinline__ void st_rel(unsigned* p, unsigned v) {
    asm volatile("st.release.gpu.global.u32 [%0], %1;" :: "l"(p), "r"(v) : "memory");
}
__device__ __forceinline__ void red_rel_add(unsigned* p, unsigned v) {
    asm volatile("red.release.gpu.global.add.u32 [%0], %1;" :: "l"(p), "r"(v) : "memory");
}
__device__ __forceinline__ void stv2_cg(float* p, float a, float b) {
    asm volatile("st.global.cg.v2.f32 [%0], {%1,%2};" :: "l"(p), "f"(a), "f"(b) : "memory");
}
__device__ __forceinline__ float frcp(float x) {
    float r;
    asm("rcp.approx.f32 %0, %1;" : "=f"(r) : "f"(x));
    return r;
}

// -------- init kernel --------
__global__ void crf_init(const float* __restrict__ T) {
    int idx = blockIdx.x * blockDim.x + threadIdx.x;
    if (idx < C*C) {
        float e = expf(T[idx]);
        g_E[idx] = e;
        int k = idx / C, j = idx % C;
        g_ET[j*C + k] = e;
    }
    if (idx < 2*NCTA*FSTRIDE)     ((unsigned*)g_cnt)[idx] = 0u;
    if (idx < NCTA_TOTAL*FSTRIDE) g_jflags[idx] = 0u;
}

// -------- persistent forward+backward kernel --------
__global__ void __launch_bounds__(NTHREADS, 1) crf_main(const float* __restrict__ scores,
                                                        float* __restrict__ out) {
    const int  cta    = blockIdx.x;
    const bool isBeta = (cta >= NCTA);
    const int  dir    = isBeta ? 1 : 0;
    const int  grp    = isBeta ? (cta - NCTA) : cta;
    const int  warp   = threadIdx.x >> 5;
    const int  lane   = threadIdx.x & 31;
    const int  j0     = grp * 16 + warp * 2;   // 2 columns per warp

    __shared__ __align__(16) float q_sm[2][C];     // double-buffered q vector
    __shared__ float redsum[NWARP];
    __shared__ float k_sm[ROWS_PER_CTA];

    // E coefficients for this warp's two columns: 64 regs/thread.
    float4 Ea[8], Eb[8];
    {
        const float* Emat = isBeta ? g_E : g_ET;
        const float4* Ra = (const float4*)(Emat + (size_t)j0 * C);
        const float4* Rb = (const float4*)(Emat + (size_t)(j0 + 1) * C);
        #pragma unroll
        for (int u = 0; u < 8; u++) { Ea[u] = Ra[u*32 + lane]; Eb[u] = Rb[u*32 + lane]; }
    }

    float*    rowsOut = isBeta ? g_beta : out;   // centered alpha -> d_out
    double*   offArr  = isBeta ? g_offB : g_offA;
    unsigned* cntArr  = g_cnt[dir];

    double Cd = 0.0;
    const bool keeper = (grp == 0 && warp == 0);   // checked under lane==0

    // ---- step 0: publish q0 = exp(scores[row0]) into buffer 0, announce
    float2 s_pref = make_float2(0.f, 0.f), es_pref = make_float2(0.f, 0.f);
    {
        const int row0 = isBeta ? (NSENT - 1) : 0;
        if (lane == 0) {
            float2 s0 = *(const float2*)&scores[(size_t)row0 * C + j0];
            *(float2*)&rowsOut[(size_t)row0 * C + j0] = s0;
            stv2_cg(&g_q[dir][0][j0], expf(s0.x), expf(s0.y));
            red_rel_add(&cntArr[grp*FSTRIDE], 1u);       // 8 increments/step
            const int row1 = isBeta ? (NSENT - 2) : 1;
            s_pref = *(const float2*)&scores[(size_t)row1 * C + j0];
            es_pref = make_float2(expf(s_pref.x), expf(s_pref.y));
            if (keeper) offArr[row0] = 0.0;
        }
    }

    // ---- main recurrence: 8191 dependent rounds
    for (int t = 1; t < NSENT; t++) {
        const int row = isBeta ? (NSENT - 1 - t) : t;
        const int buf = (t - 1) & 1;

        float2 sv  = s_pref;
        float2 esv = es_pref;
        if (lane == 0) {
            int tn = (t + 1 < NSENT) ? (t + 1) : t;
            int rown = isBeta ? (NSENT - 1 - tn) : tn;
            s_pref = *(const float2*)&scores[(size_t)rown * C + j0];
        }

        // detect + fetch: threads 0..63 poll one counter each, then fetch
        // that producer's 64B (16 floats) coalesced.
        if (threadIdx.x < NCTA) {
            const int g = threadIdx.x;
            const unsigned want = (unsigned)(NWARP * t);  // 8 increments/step
            while (ld_acq(&cntArr[g*FSTRIDE]) < want) { }
            const float4* src = (const float4*)(g_q[dir][buf] + g*16);
            float4 v0 = __ldcg(&src[0]);
            float4 v1 = __ldcg(&src[1]);
            float4 v2 = __ldcg(&src[2]);
            float4 v3 = __ldcg(&src[3]);
            float4* dst = (float4*)&q_sm[buf][g*16];
            dst[0] = v0; dst[1] = v1; dst[2] = v2; dst[3] = v3;
        }
        __syncthreads();     // the ONLY per-step CTA barrier

        // matvec for 2 columns + running max (q loaded once, used 3x)
        float aa0=0.f,aa1=0.f,aa2=0.f,aa3=0.f;
        float ab0=0.f,ab1=0.f,ab2=0.f,ab3=0.f;
        float mm0=0.f,mm1=0.f,mm2=0.f,mm3=0.f;
        const float4* p4 = (const float4*)q_sm[buf];
        #pragma unroll
        for (int u = 0; u < 8; u++) {
            float4 p = p4[u*32 + lane];
            aa0 = fmaf(p.x, Ea[u].x, aa0);  ab0 = fmaf(p.x, Eb[u].x, ab0);  mm0 = fmaxf(mm0, p.x);
            aa1 = fmaf(p.y, Ea[u].y, aa1);  ab1 = fmaf(p.y, Eb[u].y, ab1);  mm1 = fmaxf(mm1, p.y);
            aa2 = fmaf(p.z, Ea[u].z, aa2);  ab2 = fmaf(p.z, Eb[u].z, ab2);  mm2 = fmaxf(mm2, p.z);
            aa3 = fmaf(p.w, Ea[u].w, aa3);  ab3 = fmaf(p.w, Eb[u].w, ab3);  mm3 = fmaxf(mm3, p.w);
        }
        float acca = (aa0+aa1)+(aa2+aa3);
        float accb = (ab0+ab1)+(ab2+ab3);
        float mxp  = fmaxf(fmaxf(mm0,mm1), fmaxf(mm2,mm3));
        #pragma unroll
        for (int s = 16; s > 0; s >>= 1) {
            acca += __shfl_xor_sync(0xFFFFFFFFu, acca, s);
            accb += __shfl_xor_sync(0xFFFFFFFFu, accb, s);
            mxp   = fmaxf(mxp, __shfl_xor_sync(0xFFFFFFFFu, mxp, s));
        }

        if (lane == 0) {
            // ---- ON critical path: rcp + muls + one v2 store + one RMW
            float r  = frcp(mxp);             // bitwise identical in every CTA
            float qa = esv.x * acca * r;
            float qb = esv.y * accb * r;
            stv2_cg(&g_q[dir][t & 1][j0], qa, qb);
            red_rel_add(&cntArr[grp*FSTRIDE], 1u);
            // ---- OFF critical path
            float2 ah = make_float2(sv.x + logf(acca), sv.y + logf(accb));
            *(float2*)&rowsOut[(size_t)row * C + j0] = ah;
            if (keeper) {
                offArr[row] = Cd;
                Cd -= (double)logf(r);
            }
            es_pref = make_float2(expf(s_pref.x), expf(s_pref.y));
        }
    }

    // final rowsOut/offArr stores must happen-before the join release
    __syncthreads();
    if (keeper && threadIdx.x == 0 && !isBeta) g_Zbase = Cd;
    __threadfence();
    __syncthreads();

    // ---- join both directions (release/acquire flag barrier)
    if (threadIdx.x == 0) st_rel(&g_jflags[cta*FSTRIDE], 1u);
    if (threadIdx.x < NCTA_TOTAL) {
        const unsigned* fp = &g_jflags[threadIdx.x * FSTRIDE];
        while (ld_acq(fp) < 1u) { }
    }
    __syncthreads();

    // ---- Z = Zbase + log(sum q_final) (final alpha q in g_q[0][1])
    double Zd;
    {
        float4 v = __ldcg(&((const float4*)g_q[0][1])[threadIdx.x]);  // 256 float4
        float zs = (v.x + v.y) + (v.z + v.w);
        #pragma unroll
        for (int s = 16; s > 0; s >>= 1)
            zs += __shfl_xor_sync(0xFFFFFFFFu, zs, s);
        if (lane == 0) redsum[warp] = zs;
        __syncthreads();
        if (warp == 0) {
            float s = (lane < NWARP) ? redsum[lane] : 0.0f;
            #pragma unroll
            for (int sh = 4; sh > 0; sh >>= 1)
                s += __shfl_xor_sync(0xFFFFFFFFu, s, sh);
            if (lane == 0) redsum[0] = s;
        }
        __syncthreads();
        Zd = g_Zbase + (double)logf(redsum[0]);
    }

    // ---- per-row combine constants K[i] = offA[i] + offB[i] - Z
    const int rbase = cta * ROWS_PER_CTA;
    if (threadIdx.x < ROWS_PER_CTA) {
        int row = rbase + threadIdx.x;
        k_sm[threadIdx.x] = (float)(g_offA[row] + g_offB[row] - Zd);
    }
    __syncthreads();

    // ---- marginals: out = a_hat(out) + b_hat - scores + K[row]
    {
        const float4* b4 = (const float4*)g_beta;
        const float4* s4 = (const float4*)scores;
        float4* o4 = (float4*)out;
        const size_t base4 = (size_t)rbase * (C/4);
        const int    n4    = ROWS_PER_CTA * (C/4);
        for (int idx = threadIdx.x; idx < n4; idx += NTHREADS) {
            int   rl = idx >> 8;
            float K  = k_sm[rl];
            size_t i = base4 + idx;
            float4 av = __ldcg(&o4[i]);
            float4 b  = __ldcg(&b4[i]);
            float4 s  = __ldg(&s4[i]);
            float4 r;
            r.x = av.x + b.x - s.x + K;
            r.y = av.y + b.y - s.y + K;
            r.z = av.z + b.z - s.z + K;
            r.w = av.w + b.w - s.w + K;
            o4[i] = r;
        }
    }
}

extern "C" void kernel_launch(void* const* d_in, const int* in_sizes, int n_in,
                              void* d_out, int out_size) {
    const float* scores = (const float*)d_in[0];   // [8192*1024] f32
    const float* T      = (const float*)d_in[1];   // [1024*1024] f32
    float* out = (float*)d_out;                    // [8192*1024] f32

    crf_init<<<(C*C + 255) / 256, 256>>>(T);
    crf_main<<<NCTA_TOTAL, NTHREADS>>>(scores, out);
}